// round 7
// baseline (speedup 1.0000x reference)
#include <cuda_runtime.h>
#include <cuda_bf16.h>
#include <math.h>

#define C_CH   128
#define HW     3136          // 56*56
#define B_SZ   64
#define NCHUNK 8
#define NTOT   (B_SZ * HW)   // 200704 elements per channel
#define HW4    (HW / 4)      // 784 float4 per (b,c) plane
#define NPLANE (B_SZ * C_CH) // 8192 planes
#define CHUNKS_PER_PLANE (HW / 16)            // 196 chunks of 16 elems
#define NCHUNKS_TOTAL (NPLANE * CHUNKS_PER_PLANE)  // 1,605,632

// scratch (no device allocation allowed)
__device__ __align__(128) __nv_bfloat16 g_xq[(size_t)NPLANE * HW];  // 51.4 MB bf16 copy
__device__ float g_pmax[NPLANE];
__device__ float g_pmin[NPLANE];
__device__ float g_psum[NPLANE];
__device__ float g_avg [C_CH];
__device__ float g_scale[C_CH];
__device__ float g_gam [C_CH];

__device__ __forceinline__ float qbf(float v) {
    return __bfloat162float(__float2bfloat16(v));
}

// 32B store, pinned in L2 (evict_last)
__device__ __forceinline__ void st_el8(__nv_bfloat16* p, const unsigned r[8]) {
    asm volatile("st.global.L2::evict_last.v8.b32 [%0], {%1,%2,%3,%4,%5,%6,%7,%8};"
                 :: "l"(p), "r"(r[0]), "r"(r[1]), "r"(r[2]), "r"(r[3]),
                    "r"(r[4]), "r"(r[5]), "r"(r[6]), "r"(r[7]) : "memory");
}
// 32B load (evict_last form — the only v8 form known to compile on sm_103)
__device__ __forceinline__ void ld_el8(const __nv_bfloat16* p, unsigned r[8]) {
    asm("ld.global.L2::evict_last.v8.b32 {%0,%1,%2,%3,%4,%5,%6,%7}, [%8];"
        : "=r"(r[0]), "=r"(r[1]), "=r"(r[2]), "=r"(r[3]),
          "=r"(r[4]), "=r"(r[5]), "=r"(r[6]), "=r"(r[7]) : "l"(p));
}

// ---------------------------------------------------------------------------
// Pass 1: one WARP per plane. Streaming-read x (evict_first), compute
// max/min/sum, and write the bf16-quantized copy pinned in L2.
// Per thread-step: 4x float4 loads (64B x) -> 1x 32B bf16 store.
// Plane = 196 chunks of 16 elems: 6 warp-rounds + 4-lane tail.
// ---------------------------------------------------------------------------
__global__ void __launch_bounds__(256) stats_kernel(const float* __restrict__ x) {
    const int warp = threadIdx.x >> 5;
    const int lane = threadIdx.x & 31;
    const int p    = blockIdx.x * 8 + warp;

    const float4* px = reinterpret_cast<const float4*>(x + (size_t)p * HW);
    __nv_bfloat16* pq = g_xq + (size_t)p * HW;

    float vmax = -INFINITY, vmin = INFINITY, vsum = 0.0f;

    #define DO_CHUNK(CHUNK)                                                     \
    {                                                                           \
        const int b4 = (CHUNK) * 4;                                             \
        float4 a = __ldcs(px + b4);                                             \
        float4 b = __ldcs(px + b4 + 1);                                         \
        float4 c = __ldcs(px + b4 + 2);                                         \
        float4 d = __ldcs(px + b4 + 3);                                         \
        unsigned rq[8];                                                         \
        __nv_bfloat162 h;                                                       \
        float2 f;                                                               \
        /* pack to bf16x2, unpack for exact quantized sum */                    \
        h = __floats2bfloat162_rn(a.x, a.y); rq[0] = *(unsigned*)&h;            \
        f = __bfloat1622float2(h); vsum += f.x + f.y;                           \
        h = __floats2bfloat162_rn(a.z, a.w); rq[1] = *(unsigned*)&h;            \
        f = __bfloat1622float2(h); vsum += f.x + f.y;                           \
        h = __floats2bfloat162_rn(b.x, b.y); rq[2] = *(unsigned*)&h;            \
        f = __bfloat1622float2(h); vsum += f.x + f.y;                           \
        h = __floats2bfloat162_rn(b.z, b.w); rq[3] = *(unsigned*)&h;            \
        f = __bfloat1622float2(h); vsum += f.x + f.y;                           \
        h = __floats2bfloat162_rn(c.x, c.y); rq[4] = *(unsigned*)&h;            \
        f = __bfloat1622float2(h); vsum += f.x + f.y;                           \
        h = __floats2bfloat162_rn(c.z, c.w); rq[5] = *(unsigned*)&h;            \
        f = __bfloat1622float2(h); vsum += f.x + f.y;                           \
        h = __floats2bfloat162_rn(d.x, d.y); rq[6] = *(unsigned*)&h;            \
        f = __bfloat1622float2(h); vsum += f.x + f.y;                           \
        h = __floats2bfloat162_rn(d.z, d.w); rq[7] = *(unsigned*)&h;            \
        f = __bfloat1622float2(h); vsum += f.x + f.y;                           \
        /* raw-fp32 min/max (qbf monotonic; quantized in finalize) */           \
        vmax = fmaxf(vmax, fmaxf(fmaxf(fmaxf(a.x, a.y), fmaxf(a.z, a.w)),       \
                                 fmaxf(fmaxf(b.x, b.y), fmaxf(b.z, b.w))));     \
        vmax = fmaxf(vmax, fmaxf(fmaxf(fmaxf(c.x, c.y), fmaxf(c.z, c.w)),       \
                                 fmaxf(fmaxf(d.x, d.y), fmaxf(d.z, d.w))));     \
        vmin = fminf(vmin, fminf(fminf(fminf(a.x, a.y), fminf(a.z, a.w)),       \
                                 fminf(fminf(b.x, b.y), fminf(b.z, b.w))));     \
        vmin = fminf(vmin, fminf(fminf(fminf(c.x, c.y), fminf(c.z, c.w)),       \
                                 fminf(fminf(d.x, d.y), fminf(d.z, d.w))));     \
        st_el8(pq + (CHUNK) * 16, rq);                                          \
    }

    #pragma unroll
    for (int r = 0; r < 6; ++r) {
        const int chunk = r * 32 + lane;
        DO_CHUNK(chunk)
    }
    if (lane < 4) {
        const int chunk = 192 + lane;
        DO_CHUNK(chunk)
    }
    #undef DO_CHUNK

    #pragma unroll
    for (int o = 16; o > 0; o >>= 1) {
        vmax = fmaxf(vmax, __shfl_down_sync(0xFFFFFFFFu, vmax, o));
        vmin = fminf(vmin, __shfl_down_sync(0xFFFFFFFFu, vmin, o));
        vsum +=            __shfl_down_sync(0xFFFFFFFFu, vsum, o);
    }
    if (lane == 0) {
        g_pmax[p] = vmax;
        g_pmin[p] = vmin;
        g_psum[p] = vsum;
    }
}

// ---------------------------------------------------------------------------
// Pass 2: per-channel scalars (1 block, 128 threads).
// ---------------------------------------------------------------------------
__global__ void finalize_kernel(const float* __restrict__ gamma) {
    const int c = threadIdx.x;

    float sm = 0.f, sn = 0.f, st = 0.f;
    #pragma unroll
    for (int k = 0; k < NCHUNK; ++k) {
        float cmax = -INFINITY, cmin = INFINITY, cs = 0.f;
        #pragma unroll
        for (int b = 0; b < 8; ++b) {
            const int p = (8 * k + b) * C_CH + c;
            cmax = fmaxf(cmax, g_pmax[p]);
            cmin = fminf(cmin, g_pmin[p]);
            cs  += g_psum[p];
        }
        sm += qbf(cmax);
        sn += qbf(cmin);
        st += cs;
    }
    const float sum_max = qbf(sm);
    const float sum_min = qbf(sn);
    const float avg_max = qbf(sum_max / (float)NCHUNK);
    const float avg_min = qbf(sum_min / (float)NCHUNK);
    const float total   = qbf(st);

    const double chunk_size = (double)(NCHUNK * HW);  // 25088
    const float scale_fix = (float)(1.0 / sqrt(2.0 * log(chunk_size)));

    g_avg[c]   = qbf(total / (float)NTOT);
    g_scale[c] = qbf(1.0f / ((avg_max - avg_min) * scale_fix + 1e-5f));
    g_gam[c]   = qbf(gamma[c]);
}

// ---------------------------------------------------------------------------
// Pass 3: one 16-elem chunk per thread. Read xq (L2-resident bf16),
// compute, store out (__stcs), then DISCARD the consumed xq lines so the
// dirty scratch never writes back to DRAM.
// ---------------------------------------------------------------------------
__global__ void __launch_bounds__(256) norm_kernel(const float* __restrict__ beta,
                                                   float* __restrict__ out) {
    const int chunk = blockIdx.x * 256 + threadIdx.x;   // 0..1605631
    const int c = (chunk / CHUNKS_PER_PLANE) & (C_CH - 1);

    const float avg   = g_avg[c];
    const float scale = g_scale[c];
    const float g     = g_gam[c];
    const float be    = beta[c];

    const __nv_bfloat16* pq = g_xq + (size_t)chunk * 16;
    unsigned rq[8];
    ld_el8(pq, rq);

    float4* po = reinterpret_cast<float4*>(out) + (size_t)chunk * 4;

    #pragma unroll
    for (int i = 0; i < 4; ++i) {
        __nv_bfloat162 h0 = *(__nv_bfloat162*)&rq[2 * i];
        __nv_bfloat162 h1 = *(__nv_bfloat162*)&rq[2 * i + 1];
        float2 f0 = __bfloat1622float2(h0);
        float2 f1 = __bfloat1622float2(h1);
        float4 r; float t;
        t = qbf((f0.x - avg) * scale); r.x = qbf(t * g + be);
        t = qbf((f0.y - avg) * scale); r.y = qbf(t * g + be);
        t = qbf((f1.x - avg) * scale); r.z = qbf(t * g + be);
        t = qbf((f1.y - avg) * scale); r.w = qbf(t * g + be);
        __stcs(po + i, r);
    }

    // Drop the consumed scratch line (128B = 4 chunks). Safe: by the time the
    // warp issues this, every lane's load data has been consumed (stores above
    // depend on it), so no in-flight read can see the invalidated line.
    if ((chunk & 3) == 0) {
        asm volatile("discard.global.L2 [%0], 128;" :: "l"(pq) : "memory");
    }
}

// ---------------------------------------------------------------------------
extern "C" void kernel_launch(void* const* d_in, const int* in_sizes, int n_in,
                              void* d_out, int out_size) {
    const float* x     = (const float*)d_in[0];
    const float* gamma = (const float*)d_in[1];
    const float* beta  = (const float*)d_in[2];
    float* out = (float*)d_out;

    stats_kernel<<<NPLANE / 8, 256>>>(x);
    finalize_kernel<<<1, C_CH>>>(gamma);
    norm_kernel<<<NCHUNKS_TOTAL / 256, 256>>>(beta, out);
}

// round 8
// speedup vs baseline: 1.3234x; 1.3234x over previous
#include <cuda_runtime.h>
#include <cuda_bf16.h>
#include <math.h>

#define C_CH   128
#define HW     3136          // 56*56
#define B_SZ   64
#define NCHUNK 8
#define NTOT   (B_SZ * HW)   // 200704 elements per channel
#define HW4    (HW / 4)      // 784 float4 per (b,c) plane
#define NPLANE (B_SZ * C_CH) // 8192 planes
#define STATS_GRID (NPLANE / 8)

// scratch (no device allocation allowed)
__device__ float g_pmax[NPLANE];   // raw (unquantized) per-plane max
__device__ float g_pmin[NPLANE];
__device__ float g_psum[NPLANE];   // fp32 sum of bf16-quantized elements
__device__ float g_avg [C_CH];
__device__ float g_scale[C_CH];
__device__ float g_gam [C_CH];     // quantized gamma
__device__ unsigned g_done = 0;    // last-block-done counter (reset each launch)

__device__ __forceinline__ float qbf(float v) {
    // bf16 round-to-nearest-even round trip == jnp astype(bf16).astype(f32)
    return __bfloat162float(__float2bfloat16(v));
}

// 32-byte global load with L2 evict_last hint (sm_103 requires .v8.b32 form)
__device__ __forceinline__ void ldg_el8(const float* p, float v[8]) {
    unsigned r0, r1, r2, r3, r4, r5, r6, r7;
    asm volatile("ld.global.L2::evict_last.v8.b32 {%0,%1,%2,%3,%4,%5,%6,%7}, [%8];"
                 : "=r"(r0), "=r"(r1), "=r"(r2), "=r"(r3),
                   "=r"(r4), "=r"(r5), "=r"(r6), "=r"(r7)
                 : "l"(p));
    v[0] = __uint_as_float(r0); v[1] = __uint_as_float(r1);
    v[2] = __uint_as_float(r2); v[3] = __uint_as_float(r3);
    v[4] = __uint_as_float(r4); v[5] = __uint_as_float(r5);
    v[6] = __uint_as_float(r6); v[7] = __uint_as_float(r7);
}

// ---------------------------------------------------------------------------
// Pass 1: one WARP per (b,c) plane — pure linear stream per block.
// 256-bit loads tagged L2::evict_last so x stays resident for the norm pass.
// The LAST block to finish also runs the per-channel finalize (no extra
// kernel launch).
// ---------------------------------------------------------------------------
__global__ void __launch_bounds__(256) stats_kernel(const float* __restrict__ x,
                                                    const float* __restrict__ gamma) {
    const int warp = threadIdx.x >> 5;
    const int lane = threadIdx.x & 31;
    const int tid  = threadIdx.x;
    const int p    = blockIdx.x * 8 + warp;        // plane id 0..8191

    const float* px = x + (size_t)p * HW;

    float vmax = -INFINITY, vmin = INFINITY, vsum = 0.0f;

    #define ACC8(V)                                                           \
        vmax = fmaxf(vmax, fmaxf(fmaxf(fmaxf((V)[0], (V)[1]), fmaxf((V)[2], (V)[3])), \
                                 fmaxf(fmaxf((V)[4], (V)[5]), fmaxf((V)[6], (V)[7])))); \
        vmin = fminf(vmin, fminf(fminf(fminf((V)[0], (V)[1]), fminf((V)[2], (V)[3])), \
                                 fminf(fminf((V)[4], (V)[5]), fminf((V)[6], (V)[7])))); \
        vsum += ((qbf((V)[0]) + qbf((V)[1])) + (qbf((V)[2]) + qbf((V)[3])))   \
              + ((qbf((V)[4]) + qbf((V)[5])) + (qbf((V)[6]) + qbf((V)[7])));

    // 392 x 32B per plane = 3*(4*32) + 8 : three unroll-4 groups + tail
    #pragma unroll
    for (int gidx = 0; gidx < 3; ++gidx) {
        const int base = (gidx * 128 + lane) * 8;
        float v0[8], v1[8], v2[8], v3[8];
        ldg_el8(px + base,          v0);
        ldg_el8(px + base + 32 * 8, v1);
        ldg_el8(px + base + 64 * 8, v2);
        ldg_el8(px + base + 96 * 8, v3);
        ACC8(v0) ACC8(v1) ACC8(v2) ACC8(v3)
    }
    if (lane < 8) {
        float v[8];
        ldg_el8(px + (384 + lane) * 8, v);
        ACC8(v)
    }
    #undef ACC8

    // warp reduce
    #pragma unroll
    for (int o = 16; o > 0; o >>= 1) {
        vmax = fmaxf(vmax, __shfl_down_sync(0xFFFFFFFFu, vmax, o));
        vmin = fminf(vmin, __shfl_down_sync(0xFFFFFFFFu, vmin, o));
        vsum +=            __shfl_down_sync(0xFFFFFFFFu, vsum, o);
    }
    if (lane == 0) {
        g_pmax[p] = vmax;   // raw; quantized after chunk-max (monotonic)
        g_pmin[p] = vmin;
        g_psum[p] = vsum;
    }

    // ---- last-block-done: fold the per-channel finalize in here -----------
    __shared__ unsigned s_last;
    __threadfence();                       // publish g_p* before the count
    if (tid == 0) {
        unsigned t = atomicAdd(&g_done, 1u);
        s_last = (t == STATS_GRID - 1) ? 1u : 0u;
    }
    __syncthreads();
    if (s_last) {
        __threadfence();                   // acquire all blocks' g_p* writes
        if (tid < C_CH) {
            const int c = tid;
            float sm = 0.f, sn = 0.f, st = 0.f;
            #pragma unroll
            for (int k = 0; k < NCHUNK; ++k) {
                float cmax = -INFINITY, cmin = INFINITY, cs = 0.f;
                #pragma unroll
                for (int b = 0; b < 8; ++b) {
                    const int pp = (8 * k + b) * C_CH + c;
                    cmax = fmaxf(cmax, g_pmax[pp]);
                    cmin = fminf(cmin, g_pmin[pp]);
                    cs  += g_psum[pp];
                }
                sm += qbf(cmax);   // chunk-max of quantized == q(raw chunk max)
                sn += qbf(cmin);
                st += cs;
            }
            const float sum_max = qbf(sm);
            const float sum_min = qbf(sn);
            const float avg_max = qbf(sum_max / (float)NCHUNK);
            const float avg_min = qbf(sum_min / (float)NCHUNK);
            const float total   = qbf(st);

            const double chunk_size = (double)(NCHUNK * HW);  // 25088
            const float scale_fix = (float)(1.0 / sqrt(2.0 * log(chunk_size)));

            g_avg[c]   = qbf(total / (float)NTOT);
            g_scale[c] = qbf(1.0f / ((avg_max - avg_min) * scale_fix + 1e-5f));
            g_gam[c]   = qbf(gamma[c]);
        }
        if (tid == 0) g_done = 0;          // reset for the next graph replay
    }
}

// ---------------------------------------------------------------------------
// Pass 2: out = q( q((q(x) - avg) * scale) * q(gamma) + beta )
// Plane order REVERSED: the planes stats filled most recently (high ids) are
// read first, while still L2-resident. Reads via __ldcs (demote after the
// one re-use), writes via __stcs (don't let output churn L2).
// ---------------------------------------------------------------------------
__global__ void __launch_bounds__(256) norm_kernel(const float* __restrict__ x,
                                                   const float* __restrict__ beta,
                                                   float* __restrict__ out) {
    const int bc = (NPLANE - 1) - blockIdx.x;    // reversed plane order
    const int c  = bc & (C_CH - 1);

    const float avg   = g_avg[c];
    const float scale = g_scale[c];
    const float g     = g_gam[c];
    const float be    = beta[c];

    const float4* px = reinterpret_cast<const float4*>(x)   + (size_t)bc * HW4;
    float4*       po = reinterpret_cast<float4*>(out)       + (size_t)bc * HW4;

    const int tid = threadIdx.x;
    float4 v0 = __ldcs(px + tid);
    float4 v1 = __ldcs(px + tid + 256);
    float4 v2 = __ldcs(px + tid + 512);
    float4 v3;
    if (tid < 16) v3 = __ldcs(px + tid + 768);

    float4 r; float t;
    #define NORM4(V, R)                                               \
        t = qbf((qbf((V).x) - avg) * scale); (R).x = qbf(t * g + be); \
        t = qbf((qbf((V).y) - avg) * scale); (R).y = qbf(t * g + be); \
        t = qbf((qbf((V).z) - avg) * scale); (R).z = qbf(t * g + be); \
        t = qbf((qbf((V).w) - avg) * scale); (R).w = qbf(t * g + be);

    NORM4(v0, r); __stcs(po + tid,       r);
    NORM4(v1, r); __stcs(po + tid + 256, r);
    NORM4(v2, r); __stcs(po + tid + 512, r);
    if (tid < 16) { NORM4(v3, r); __stcs(po + tid + 768, r); }
    #undef NORM4
}

// ---------------------------------------------------------------------------
extern "C" void kernel_launch(void* const* d_in, const int* in_sizes, int n_in,
                              void* d_out, int out_size) {
    const float* x     = (const float*)d_in[0];
    const float* gamma = (const float*)d_in[1];
    const float* beta  = (const float*)d_in[2];
    float* out = (float*)d_out;

    stats_kernel<<<STATS_GRID, 256>>>(x, gamma);
    norm_kernel<<<NPLANE, 256>>>(x, beta, out);
}